// round 14
// baseline (speedup 1.0000x reference)
#include <cuda_runtime.h>
#include <cuda_bf16.h>
#include <cuda_fp16.h>
#include <cstdint>

#define L_RES 512
#define C_S   256
#define C_Z   128
#define LN_EPS 1e-5f

#define GRID_PAIR 296
#define NUNITS 1280

// ---------------------------------------------------------------------------
// Device scratch
// ---------------------------------------------------------------------------
__device__ __align__(16) float g_u[L_RES * C_S];         // LayerNorm'd embeddings
__device__ __align__(16) float g_zjb[L_RES * C_Z];       // u @ W2 + b_pair
__device__ __align__(16) float g_zib[L_RES * C_Z];       // u @ W1
__device__ __align__(16) __half g_w3t[C_Z * C_S];        // W3^T fp16 [z][c]
__device__ __align__(16) __half g_u16[L_RES * C_S];      // fp16(u)   [i][c]
__device__ __align__(16) __half g_ball[L_RES * C_Z * C_S]; // B_all[j][z][c]=fp16(u[j,c]*W3[c,z])

// ---------------------------------------------------------------------------
// Base-PTX helpers (valid on compute_103)
// ---------------------------------------------------------------------------
__device__ __forceinline__ uint32_t smem_u32(const void* p) {
    uint32_t a;
    asm("{ .reg .u64 t; cvta.to.shared.u64 t, %1; cvt.u32.u64 %0, t; }"
        : "=r"(a) : "l"(p));
    return a;
}

__device__ __forceinline__ void ldsm_x4(uint32_t& r0, uint32_t& r1,
                                        uint32_t& r2, uint32_t& r3, uint32_t addr) {
    asm volatile("ldmatrix.sync.aligned.m8n8.x4.shared.b16 {%0,%1,%2,%3}, [%4];"
                 : "=r"(r0), "=r"(r1), "=r"(r2), "=r"(r3) : "r"(addr));
}

__device__ __forceinline__ void mma16816(float* c, const uint32_t* a, const uint32_t* b) {
    asm volatile(
        "mma.sync.aligned.m16n8k16.row.col.f32.f16.f16.f32 "
        "{%0,%1,%2,%3}, {%4,%5,%6,%7}, {%8,%9}, {%0,%1,%2,%3};"
        : "+f"(c[0]), "+f"(c[1]), "+f"(c[2]), "+f"(c[3])
        : "r"(a[0]), "r"(a[1]), "r"(a[2]), "r"(a[3]), "r"(b[0]), "r"(b[1]));
}

#define CP_ASYNC16(dst, src) \
    asm volatile("cp.async.cg.shared.global [%0], [%1], 16;" :: "r"(dst), "l"(src))
#define CP_COMMIT() asm volatile("cp.async.commit_group;")
#define CP_WAIT1()  asm volatile("cp.async.wait_group 1;")
#define CP_WAIT0()  asm volatile("cp.async.wait_group 0;")

// ---------------------------------------------------------------------------
// Kernel 1: grid 128, block 256. Pure gather + LN (warp per row) + W3 fold.
// (R13 version — measured 5.3us)
// ---------------------------------------------------------------------------
__global__ void prep_kernel(const int* __restrict__ seq,
                            const int* __restrict__ chain,
                            const int* __restrict__ ridx,
                            const float* __restrict__ E_aa,
                            const float* __restrict__ E_pos,
                            const float* __restrict__ E_chain,
                            const float* __restrict__ W_pair,
                            const float* __restrict__ ln_w,
                            const float* __restrict__ ln_b,
                            float* __restrict__ out_s)
{
    const int t = threadIdx.x, lane = t & 31, w = t >> 5;
    const int b = blockIdx.x, i0 = b * 4;

    if (w < 4) {
        const int i = i0 + w;
        const int sq = seq[i], ci = chain[i], ri = ridx[i];
        const int c0 = lane * 8;

        const float4* pa = (const float4*)(E_aa + (size_t)sq * C_S + c0);
        const float4* pp = (const float4*)(E_pos + (size_t)ri * C_S + c0);
        const float4* pc = (const float4*)(E_chain + (size_t)ci * C_S + c0);
        float4 a0 = pa[0], a1 = pa[1];
        float4 p0 = pp[0], p1 = pp[1];
        float4 q0 = pc[0], q1 = pc[1];
        float v[8];
        v[0] = a0.x + p0.x + q0.x; v[1] = a0.y + p0.y + q0.y;
        v[2] = a0.z + p0.z + q0.z; v[3] = a0.w + p0.w + q0.w;
        v[4] = a1.x + p1.x + q1.x; v[5] = a1.y + p1.y + q1.y;
        v[6] = a1.z + p1.z + q1.z; v[7] = a1.w + p1.w + q1.w;

        *(float4*)(out_s + (size_t)i * C_S + c0)     = make_float4(v[0], v[1], v[2], v[3]);
        *(float4*)(out_s + (size_t)i * C_S + c0 + 4) = make_float4(v[4], v[5], v[6], v[7]);

        float s1 = 0.f, s2 = 0.f;
        #pragma unroll
        for (int e = 0; e < 8; e++) { s1 += v[e]; s2 += v[e] * v[e]; }
        #pragma unroll
        for (int o = 16; o; o >>= 1) {
            s1 += __shfl_xor_sync(0xffffffffu, s1, o);
            s2 += __shfl_xor_sync(0xffffffffu, s2, o);
        }
        float mu = s1 * (1.f / C_S);
        float rstd = rsqrtf(s2 * (1.f / C_S) - mu * mu + LN_EPS);

        const float4* lw = (const float4*)(ln_w + c0);
        const float4* lb = (const float4*)(ln_b + c0);
        float4 w0 = lw[0], w1 = lw[1], b0 = lb[0], b1 = lb[1];
        float uu[8];
        uu[0] = (v[0] - mu) * rstd * w0.x + b0.x;
        uu[1] = (v[1] - mu) * rstd * w0.y + b0.y;
        uu[2] = (v[2] - mu) * rstd * w0.z + b0.z;
        uu[3] = (v[3] - mu) * rstd * w0.w + b0.w;
        uu[4] = (v[4] - mu) * rstd * w1.x + b1.x;
        uu[5] = (v[5] - mu) * rstd * w1.y + b1.y;
        uu[6] = (v[6] - mu) * rstd * w1.z + b1.z;
        uu[7] = (v[7] - mu) * rstd * w1.w + b1.w;

        *(float4*)(g_u + (size_t)i * C_S + c0)     = make_float4(uu[0], uu[1], uu[2], uu[3]);
        *(float4*)(g_u + (size_t)i * C_S + c0 + 4) = make_float4(uu[4], uu[5], uu[6], uu[7]);

        uint4 h16;
        __half2* hh = (__half2*)&h16;
        hh[0] = __floats2half2_rn(uu[0], uu[1]);
        hh[1] = __floats2half2_rn(uu[2], uu[3]);
        hh[2] = __floats2half2_rn(uu[4], uu[5]);
        hh[3] = __floats2half2_rn(uu[6], uu[7]);
        *(uint4*)(g_u16 + (size_t)i * C_S + c0) = h16;
    } else if (b < 64) {
        // W3^T fold: 4 consecutive elements per thread
        int id0 = b * 512 + (t - 128) * 4;
        __half tmp[4];
        #pragma unroll
        for (int k = 0; k < 4; k++) {
            int id = id0 + k;
            int z = id >> 8, c = id & 255;
            tmp[k] = __float2half_rn(W_pair[(size_t)(2 * C_S + c) * C_Z + z]);
        }
        *(uint2*)(g_w3t + id0) = *(uint2*)tmp;
    }
}

// ---------------------------------------------------------------------------
// Kernel 2: grid 256, block 256, 2 j's per block.
// zjb/zib GEMV (W reused across 2 rows) + B_all[j] = fp16(u[j,c]*W3t[z,c]).
// (R12/R13 version)
// ---------------------------------------------------------------------------
__global__ void bprep_kernel(const float* __restrict__ W_pair,
                             const float* __restrict__ b_pair)
{
    __shared__ float u_s[2][C_S];
    const int jp = blockIdx.x, t = threadIdx.x;
    const int j0 = jp * 2;

    {
        int row = t >> 7, idx = t & 127;
        float2 v = *(const float2*)(g_u + (size_t)(j0 + row) * C_S + idx * 2);
        u_s[row][idx * 2] = v.x; u_s[row][idx * 2 + 1] = v.y;
    }
    __syncthreads();

    // GEMV: t<128 -> zjb (W2 + b), t>=128 -> zib (W1); 4 chains x 2 rows
    {
        const int z = t & 127;
        const int base = (t < 128) ? C_S : 0;
        const float* Wz = W_pair + (size_t)base * C_Z + z;
        float a0[4] = {0.f, 0.f, 0.f, 0.f};
        float a1[4] = {0.f, 0.f, 0.f, 0.f};
        #pragma unroll 4
        for (int c = 0; c < C_S; c += 4) {
            #pragma unroll
            for (int q = 0; q < 4; q++) {
                float wv = Wz[(size_t)(c + q) * C_Z];
                a0[q] += u_s[0][c + q] * wv;
                a1[q] += u_s[1][c + q] * wv;
            }
        }
        float r0 = (a0[0] + a0[1]) + (a0[2] + a0[3]);
        float r1 = (a1[0] + a1[1]) + (a1[2] + a1[3]);
        if (t < 128) {
            float bp = b_pair[z];
            g_zjb[(size_t)(j0 + 0) * C_Z + z] = r0 + bp;
            g_zjb[(size_t)(j0 + 1) * C_Z + z] = r1 + bp;
        } else {
            g_zib[(size_t)(j0 + 0) * C_Z + z] = r0;
            g_zib[(size_t)(j0 + 1) * C_Z + z] = r1;
        }
    }

    // B_all for both rows
    #pragma unroll 4
    for (int k = 0; k < 32; k++) {
        int id = t + k * 256;          // 0..8191
        int jr = id >> 12;
        int rem = id & 4095;
        int z = rem >> 5, c16 = rem & 31;
        uint4 w = *(const uint4*)(g_w3t + (size_t)z * C_S + c16 * 8);
        const __half2* wh = (const __half2*)&w;
        const float2* uf = (const float2*)(u_s[jr] + c16 * 8);
        uint4 o;
        __half2* oh = (__half2*)&o;
        #pragma unroll
        for (int e = 0; e < 4; e++) {
            float2 wf = __half22float2(wh[e]);
            float2 u2 = uf[e];
            oh[e] = __floats2half2_rn(wf.x * u2.x, wf.y * u2.y);
        }
        *(uint4*)(g_ball + (size_t)(j0 + jr) * (C_Z * C_S)
                  + (size_t)z * C_S + c16 * 8) = o;
    }
}

// ---------------------------------------------------------------------------
// Kernel 3: persistent symmetric pure-GEMM pair kernel — EXACT R10 body
// (measured ~87us). Unit = (i-tile of 128, single j). 1280 units, 296 CTAs.
// ---------------------------------------------------------------------------
#define NCHUNK 4

// SMEM layout (bytes)
#define SM_A     0                    // 2 bufs x 16384               32768
#define SM_B     32768                // 2 bufs x 16384               32768
#define SM_ECP   65536                // 4 x 132 f32                   2112
#define SM_ZJB   67648                // 128 f32                        512
#define SM_ZIBJ  68160                // 128 f32                        512
#define SM_CH    68672                // 128 int                        512
#define SM_RI    69184                // 128 int                        512
#define SMEM_TOTAL 69696

__device__ __forceinline__ uint32_t sw_off(int row, int c16) {
    return (uint32_t)(row * 128 + ((c16 ^ (row & 7)) & 7) * 16);
}

__device__ __forceinline__ void stage_async(uint32_t sbase, int buf, int kcg,
                                            int i0, int j, int t)
{
    const int row = t >> 3;            // 0..31
    const int c16 = t & 7;
    const uint32_t dstA = sbase + SM_A + buf * 16384;
    const uint32_t dstB = sbase + SM_B + buf * 16384;
    const __half* srcA = g_u16 + (size_t)(i0 + row) * C_S + kcg * 64 + c16 * 8;
    const __half* srcB = g_ball + (size_t)j * (C_Z * C_S) + (size_t)row * C_S
                         + kcg * 64 + c16 * 8;
    const uint32_t sw = (uint32_t)(((c16 ^ (row & 7)) & 7) * 16 + row * 128);
    #pragma unroll
    for (int q = 0; q < 4; q++) {
        uint32_t off = sw + q * 32 * 128;
        CP_ASYNC16(dstA + off, srcA + (size_t)q * 32 * C_S);
        CP_ASYNC16(dstB + off, srcB + (size_t)q * 32 * C_S);
    }
}

__global__ __launch_bounds__(256, 2)
void pair_kernel(const int* __restrict__ chain,
                 const int* __restrict__ ridx,
                 const float* __restrict__ E_cp,
                 const float* __restrict__ E_rp,
                 float* __restrict__ out_z)
{
    extern __shared__ char smem[];
    const uint32_t sbase = smem_u32(smem);
    const int t = threadIdx.x;           // 256
    const int lane = t & 31, wid = t >> 5;
    const int wm = wid >> 2;             // 0..1  (M)
    const int wn = wid & 3;              // 0..3  (N)

    float* ecp_s = (float*)(smem + SM_ECP);
    float* zjb_s = (float*)(smem + SM_ZJB);
    float* zib_s = (float*)(smem + SM_ZIBJ);
    int*   ch_s  = (int*)  (smem + SM_CH);
    int*   ri_s  = (int*)  (smem + SM_RI);

    for (int idx = t; idx < 4 * C_Z; idx += 256)
        ecp_s[(idx >> 7) * 132 + (idx & 127)] = E_cp[idx];

    // lane address components (ldmatrix)
    const int arow_l = lane & 15;
    const int achk_l = lane >> 4;
    const int bgrp   = lane >> 3;
    const int bz_l   = ((bgrp >> 1) << 3) + (lane & 7);
    const int bco    = bgrp & 1;

    #pragma unroll 1
    for (int u = blockIdx.x; u < NUNITS; u += GRID_PAIR) {
        // decode unit -> (by, j)
        int by, j;
        if (u < 512)       { by = 0; j = u; }
        else if (u < 896)  { by = 1; j = u - 512 + 128; }
        else if (u < 1152) { by = 2; j = u - 896 + 256; }
        else               { by = 3; j = u - 1152 + 384; }
        const int i0 = by * 128;
        const bool mirror = (j >= i0 + 128);

        __syncthreads();   // previous unit fully done before restaging

        stage_async(sbase, 0, 0, i0, j, t); CP_COMMIT();
        stage_async(sbase, 1, 1, i0, j, t); CP_COMMIT();

        if (t < 128) {
            zjb_s[t] = g_zjb[(size_t)j * C_Z + t];
            zib_s[t] = g_zib[(size_t)j * C_Z + t];
        } else {
            int tt = t - 128;
            ch_s[tt] = chain[i0 + tt];
            ri_s[tt] = ridx[i0 + tt];
        }
        const int cjv = chain[j], rjv = ridx[j];

        float acc[4][4][4];
        #pragma unroll
        for (int mt = 0; mt < 4; mt++)
            #pragma unroll
            for (int nt = 0; nt < 4; nt++)
                #pragma unroll
                for (int q = 0; q < 4; q++) acc[mt][nt][q] = 0.f;

        #pragma unroll
        for (int kcg = 0; kcg < NCHUNK; kcg++) {
            if (kcg < NCHUNK - 1) { CP_WAIT1(); } else { CP_WAIT0(); }
            __syncthreads();

            const uint32_t apb = sbase + SM_A + (kcg & 1) * 16384;
            const uint32_t bpb = sbase + SM_B + (kcg & 1) * 16384;
            #pragma unroll
            for (int kk = 0; kk < 4; kk++) {
                uint32_t bh[4][2];
                #pragma unroll
                for (int pair = 0; pair < 2; pair++) {
                    int z = wn * 32 + pair * 16 + bz_l;
                    ldsm_x4(bh[pair*2][0], bh[pair*2][1],
                            bh[pair*2+1][0], bh[pair*2+1][1],
                            bpb + sw_off(z, kk * 2 + bco));
                }
                uint32_t ahf[4][4];
                #pragma unroll
                for (int mt = 0; mt < 4; mt++) {
                    int row = wm * 64 + mt * 16 + arow_l;
                    ldsm_x4(ahf[mt][0], ahf[mt][1], ahf[mt][2], ahf[mt][3],
                            apb + sw_off(row, kk * 2 + achk_l));
                }
                #pragma unroll
                for (int mt = 0; mt < 4; mt++)
                    #pragma unroll
                    for (int nt = 0; nt < 4; nt++)
                        mma16816(acc[mt][nt], ahf[mt], bh[nt]);
            }

            if (kcg < NCHUNK - 2) {
                __syncthreads();           // all warps done reading buf kcg&1
                stage_async(sbase, kcg & 1, kcg + 2, i0, j, t);
                CP_COMMIT();
            }
        }

        // ---- epilogue ----
        const int g = lane >> 2, tig = lane & 3;
        #pragma unroll
        for (int mt = 0; mt < 4; mt++) {
            #pragma unroll
            for (int h = 0; h < 2; h++) {
                int row_l = wm * 64 + mt * 16 + g + h * 8;
                int irow = i0 + row_l;
                int ci = ch_s[row_l], ri = ri_s[row_l];
                int samec = (ci == cjv);
                int dd = ri - rjv;
                int dcl = dd < -32 ? -32 : (dd > 32 ? 32 : dd);

                // direct: z[irow, j, :]
                {
                    int cp = ci * 2 + cjv;
                    int rp = samec ? (dcl + 32) : 65;
                    const float* erow = E_rp + (size_t)rp * C_Z;
                    const float* crow = ecp_s + cp * 132;
                    const float* zir  = g_zib + (size_t)irow * C_Z;
                    float* orow = out_z + ((size_t)irow * L_RES + j) * C_Z;
                    #pragma unroll
                    for (int nt = 0; nt < 4; nt++) {
                        int col = wn * 32 + nt * 8 + tig * 2;
                        float2 zi2 = *(const float2*)(zir + col);
                        float2 zj2 = *(const float2*)(zjb_s + col);
                        float2 ec2 = *(const float2*)(crow + col);
                        float2 er2 = *(const float2*)(erow + col);
                        float2 o;
                        o.x = acc[mt][nt][h * 2]     + zi2.x + zj2.x + ec2.x + er2.x;
                        o.y = acc[mt][nt][h * 2 + 1] + zi2.y + zj2.y + ec2.y + er2.y;
                        *(float2*)(orow + col) = o;
                    }
                }
                // mirror: z[j, irow, :]
                if (mirror) {
                    int cp = cjv * 2 + ci;
                    int rp = samec ? (32 - dcl) : 65;
                    const float* erow = E_rp + (size_t)rp * C_Z;
                    const float* crow = ecp_s + cp * 132;
                    const float* zjr  = g_zjb + (size_t)irow * C_Z;
                    float* orow = out_z + ((size_t)j * L_RES + irow) * C_Z;
                    #pragma unroll
                    for (int nt = 0; nt < 4; nt++) {
                        int col = wn * 32 + nt * 8 + tig * 2;
                        float2 zi2 = *(const float2*)(zib_s + col);
                        float2 zj2 = *(const float2*)(zjr + col);
                        float2 ec2 = *(const float2*)(crow + col);
                        float2 er2 = *(const float2*)(erow + col);
                        float2 o;
                        o.x = acc[mt][nt][h * 2]     + zi2.x + zj2.x + ec2.x + er2.x;
                        o.y = acc[mt][nt][h * 2 + 1] + zi2.y + zj2.y + ec2.y + er2.y;
                        *(float2*)(orow + col) = o;
                    }
                }
            }
        }
    }
}

// ---------------------------------------------------------------------------
extern "C" void kernel_launch(void* const* d_in, const int* in_sizes, int n_in,
                              void* d_out, int out_size)
{
    const int*   seq     = (const int*)  d_in[0];
    const int*   chain   = (const int*)  d_in[1];
    const int*   ridx    = (const int*)  d_in[2];
    const float* E_aa    = (const float*)d_in[3];
    const float* E_pos   = (const float*)d_in[4];
    const float* E_chain = (const float*)d_in[5];
    const float* E_cp    = (const float*)d_in[6];
    const float* E_rp    = (const float*)d_in[7];
    const float* W_pair  = (const float*)d_in[8];
    const float* b_pair  = (const float*)d_in[9];
    const float* ln_w    = (const float*)d_in[10];
    const float* ln_b    = (const float*)d_in[11];

    float* out_s = (float*)d_out;
    float* out_z = out_s + (size_t)L_RES * C_S;

    static int smem_set = 0;
    if (!smem_set) {
        cudaFuncSetAttribute(pair_kernel, cudaFuncAttributeMaxDynamicSharedMemorySize,
                             SMEM_TOTAL);
        smem_set = 1;
    }

    prep_kernel<<<128, 256>>>(seq, chain, ridx, E_aa, E_pos, E_chain,
                              W_pair, ln_w, ln_b, out_s);
    bprep_kernel<<<256, 256>>>(W_pair, b_pair);
    pair_kernel<<<GRID_PAIR, 256, SMEM_TOTAL>>>(chain, ridx, E_cp, E_rp, out_z);
}

// round 15
// speedup vs baseline: 1.0199x; 1.0199x over previous
#include <cuda_runtime.h>
#include <cuda_bf16.h>
#include <cuda_fp16.h>
#include <cstdint>

#define L_RES 512
#define C_S   256
#define C_Z   128
#define LN_EPS 1e-5f

#define GRID_PAIR 296
#define NUNITS 1280

// ---------------------------------------------------------------------------
// Device scratch
// ---------------------------------------------------------------------------
__device__ __align__(16) float g_u[L_RES * C_S];         // LayerNorm'd embeddings
__device__ __align__(16) float g_zjb[L_RES * C_Z];       // u @ W2 + b_pair
__device__ __align__(16) float g_zib[L_RES * C_Z];       // u @ W1
__device__ __align__(16) __half g_w3t[C_Z * C_S];        // W3^T fp16 [z][c]
__device__ __align__(16) __half g_u16[L_RES * C_S];      // fp16(u)   [i][c]
__device__ __align__(16) __half g_ball[L_RES * C_Z * C_S]; // B_all[j][z][c]=fp16(u[j,c]*W3[c,z])

// ---------------------------------------------------------------------------
// Base-PTX helpers (valid on compute_103)
// ---------------------------------------------------------------------------
__device__ __forceinline__ uint32_t smem_u32(const void* p) {
    uint32_t a;
    asm("{ .reg .u64 t; cvta.to.shared.u64 t, %1; cvt.u32.u64 %0, t; }"
        : "=r"(a) : "l"(p));
    return a;
}

__device__ __forceinline__ void ldsm_x4(uint32_t& r0, uint32_t& r1,
                                        uint32_t& r2, uint32_t& r3, uint32_t addr) {
    asm volatile("ldmatrix.sync.aligned.m8n8.x4.shared.b16 {%0,%1,%2,%3}, [%4];"
                 : "=r"(r0), "=r"(r1), "=r"(r2), "=r"(r3) : "r"(addr));
}

__device__ __forceinline__ void mma16816(float* c, const uint32_t* a, const uint32_t* b) {
    asm volatile(
        "mma.sync.aligned.m16n8k16.row.col.f32.f16.f16.f32 "
        "{%0,%1,%2,%3}, {%4,%5,%6,%7}, {%8,%9}, {%0,%1,%2,%3};"
        : "+f"(c[0]), "+f"(c[1]), "+f"(c[2]), "+f"(c[3])
        : "r"(a[0]), "r"(a[1]), "r"(a[2]), "r"(a[3]), "r"(b[0]), "r"(b[1]));
}

#define CP_ASYNC16(dst, src) \
    asm volatile("cp.async.cg.shared.global [%0], [%1], 16;" :: "r"(dst), "l"(src))
#define CP_COMMIT() asm volatile("cp.async.commit_group;")
#define CP_WAIT1()  asm volatile("cp.async.wait_group 1;")
#define CP_WAIT0()  asm volatile("cp.async.wait_group 0;")

// ---------------------------------------------------------------------------
// Kernel 1: grid 128, block 256. Pure gather + LN (warp per row) + W3 fold.
// (R13 version — measured 5.3-5.7us)
// ---------------------------------------------------------------------------
__global__ void prep_kernel(const int* __restrict__ seq,
                            const int* __restrict__ chain,
                            const int* __restrict__ ridx,
                            const float* __restrict__ E_aa,
                            const float* __restrict__ E_pos,
                            const float* __restrict__ E_chain,
                            const float* __restrict__ W_pair,
                            const float* __restrict__ ln_w,
                            const float* __restrict__ ln_b,
                            float* __restrict__ out_s)
{
    const int t = threadIdx.x, lane = t & 31, w = t >> 5;
    const int b = blockIdx.x, i0 = b * 4;

    if (w < 4) {
        const int i = i0 + w;
        const int sq = seq[i], ci = chain[i], ri = ridx[i];
        const int c0 = lane * 8;

        const float4* pa = (const float4*)(E_aa + (size_t)sq * C_S + c0);
        const float4* pp = (const float4*)(E_pos + (size_t)ri * C_S + c0);
        const float4* pc = (const float4*)(E_chain + (size_t)ci * C_S + c0);
        float4 a0 = pa[0], a1 = pa[1];
        float4 p0 = pp[0], p1 = pp[1];
        float4 q0 = pc[0], q1 = pc[1];
        float v[8];
        v[0] = a0.x + p0.x + q0.x; v[1] = a0.y + p0.y + q0.y;
        v[2] = a0.z + p0.z + q0.z; v[3] = a0.w + p0.w + q0.w;
        v[4] = a1.x + p1.x + q1.x; v[5] = a1.y + p1.y + q1.y;
        v[6] = a1.z + p1.z + q1.z; v[7] = a1.w + p1.w + q1.w;

        *(float4*)(out_s + (size_t)i * C_S + c0)     = make_float4(v[0], v[1], v[2], v[3]);
        *(float4*)(out_s + (size_t)i * C_S + c0 + 4) = make_float4(v[4], v[5], v[6], v[7]);

        float s1 = 0.f, s2 = 0.f;
        #pragma unroll
        for (int e = 0; e < 8; e++) { s1 += v[e]; s2 += v[e] * v[e]; }
        #pragma unroll
        for (int o = 16; o; o >>= 1) {
            s1 += __shfl_xor_sync(0xffffffffu, s1, o);
            s2 += __shfl_xor_sync(0xffffffffu, s2, o);
        }
        float mu = s1 * (1.f / C_S);
        float rstd = rsqrtf(s2 * (1.f / C_S) - mu * mu + LN_EPS);

        const float4* lw = (const float4*)(ln_w + c0);
        const float4* lb = (const float4*)(ln_b + c0);
        float4 w0 = lw[0], w1 = lw[1], b0 = lb[0], b1 = lb[1];
        float uu[8];
        uu[0] = (v[0] - mu) * rstd * w0.x + b0.x;
        uu[1] = (v[1] - mu) * rstd * w0.y + b0.y;
        uu[2] = (v[2] - mu) * rstd * w0.z + b0.z;
        uu[3] = (v[3] - mu) * rstd * w0.w + b0.w;
        uu[4] = (v[4] - mu) * rstd * w1.x + b1.x;
        uu[5] = (v[5] - mu) * rstd * w1.y + b1.y;
        uu[6] = (v[6] - mu) * rstd * w1.z + b1.z;
        uu[7] = (v[7] - mu) * rstd * w1.w + b1.w;

        *(float4*)(g_u + (size_t)i * C_S + c0)     = make_float4(uu[0], uu[1], uu[2], uu[3]);
        *(float4*)(g_u + (size_t)i * C_S + c0 + 4) = make_float4(uu[4], uu[5], uu[6], uu[7]);

        uint4 h16;
        __half2* hh = (__half2*)&h16;
        hh[0] = __floats2half2_rn(uu[0], uu[1]);
        hh[1] = __floats2half2_rn(uu[2], uu[3]);
        hh[2] = __floats2half2_rn(uu[4], uu[5]);
        hh[3] = __floats2half2_rn(uu[6], uu[7]);
        *(uint4*)(g_u16 + (size_t)i * C_S + c0) = h16;
    } else if (b < 64) {
        // W3^T fold: 4 consecutive elements per thread
        int id0 = b * 512 + (t - 128) * 4;
        __half tmp[4];
        #pragma unroll
        for (int k = 0; k < 4; k++) {
            int id = id0 + k;
            int z = id >> 8, c = id & 255;
            tmp[k] = __float2half_rn(W_pair[(size_t)(2 * C_S + c) * C_Z + z]);
        }
        *(uint2*)(g_w3t + id0) = *(uint2*)tmp;
    }
}

// ---------------------------------------------------------------------------
// Kernel 2: zjb/zib GEMV. Grid 128, block 256, 4 rows per block.
// W traffic: 128 x 256KB = 32MB (L2); 8 independent W-load chains (MLP=8)
// shared across 4 row accumulators. u rows broadcast from smem.
// ---------------------------------------------------------------------------
__global__ void gemv_kernel(const float* __restrict__ W_pair,
                            const float* __restrict__ b_pair)
{
    __shared__ float u_s[4][C_S];
    const int t = threadIdx.x;
    const int i0 = blockIdx.x * 4;

    {   // load 4 u rows (1024 floats) cooperatively
        int row = t >> 6, idx = t & 63;
        float4 v = *(const float4*)(g_u + (size_t)(i0 + row) * C_S + idx * 4);
        *(float4*)(&u_s[row][idx * 4]) = v;
    }
    __syncthreads();

    const int z = t & 127;
    const int base = (t < 128) ? C_S : 0;    // t<128: W2 (zjb), else W1 (zib)
    const float* Wz = W_pair + (size_t)base * C_Z + z;

    float acc[4][8];
    #pragma unroll
    for (int r = 0; r < 4; r++)
        #pragma unroll
        for (int q = 0; q < 8; q++) acc[r][q] = 0.f;

    #pragma unroll 2
    for (int c = 0; c < C_S; c += 8) {
        float wv[8];
        #pragma unroll
        for (int q = 0; q < 8; q++) wv[q] = Wz[(size_t)(c + q) * C_Z];
        #pragma unroll
        for (int r = 0; r < 4; r++)
            #pragma unroll
            for (int q = 0; q < 8; q++)
                acc[r][q] += u_s[r][c + q] * wv[q];
    }

    float res[4];
    #pragma unroll
    for (int r = 0; r < 4; r++)
        res[r] = ((acc[r][0] + acc[r][1]) + (acc[r][2] + acc[r][3]))
               + ((acc[r][4] + acc[r][5]) + (acc[r][6] + acc[r][7]));

    if (t < 128) {
        float bp = b_pair[z];
        #pragma unroll
        for (int r = 0; r < 4; r++)
            g_zjb[(size_t)(i0 + r) * C_Z + z] = res[r] + bp;
    } else {
        #pragma unroll
        for (int r = 0; r < 4; r++)
            g_zib[(size_t)(i0 + r) * C_Z + z] = res[r];
    }
}

// ---------------------------------------------------------------------------
// Kernel 3: B_all[j][z][c] = fp16( u[j,c] * W3t[z,c] ) ; grid 512
// (R10's exact bprep — pure streaming, ~6us)
// ---------------------------------------------------------------------------
__global__ void bprep_kernel()
{
    __shared__ float u_s[C_S];
    const int j = blockIdx.x, t = threadIdx.x;
    if (t < 128) {
        float2 v = *(const float2*)(g_u + (size_t)j * C_S + 2 * t);
        u_s[2 * t] = v.x; u_s[2 * t + 1] = v.y;
    }
    __syncthreads();

    __half* outj = g_ball + (size_t)j * (C_Z * C_S);
    #pragma unroll 4
    for (int k = 0; k < 16; k++) {
        int id = t + k * 256;          // 0..4095 uint4 chunks
        int z = id >> 5, c16 = id & 31;
        uint4 w = *(const uint4*)(g_w3t + (size_t)z * C_S + c16 * 8);
        const __half2* wh = (const __half2*)&w;
        const float2* uf = (const float2*)(u_s + c16 * 8);
        uint4 o;
        __half2* oh = (__half2*)&o;
        #pragma unroll
        for (int e = 0; e < 4; e++) {
            float2 wf = __half22float2(wh[e]);
            float2 u2 = uf[e];
            oh[e] = __floats2half2_rn(wf.x * u2.x, wf.y * u2.y);
        }
        *(uint4*)(outj + (size_t)z * C_S + c16 * 8) = o;
    }
}

// ---------------------------------------------------------------------------
// Kernel 4: persistent symmetric pure-GEMM pair kernel — EXACT R10 body.
// Unit = (i-tile of 128, single j). 1280 units, 296 CTAs.
// ---------------------------------------------------------------------------
#define NCHUNK 4

// SMEM layout (bytes)
#define SM_A     0                    // 2 bufs x 16384               32768
#define SM_B     32768                // 2 bufs x 16384               32768
#define SM_ECP   65536                // 4 x 132 f32                   2112
#define SM_ZJB   67648                // 128 f32                        512
#define SM_ZIBJ  68160                // 128 f32                        512
#define SM_CH    68672                // 128 int                        512
#define SM_RI    69184                // 128 int                        512
#define SMEM_TOTAL 69696

__device__ __forceinline__ uint32_t sw_off(int row, int c16) {
    return (uint32_t)(row * 128 + ((c16 ^ (row & 7)) & 7) * 16);
}

__device__ __forceinline__ void stage_async(uint32_t sbase, int buf, int kcg,
                                            int i0, int j, int t)
{
    const int row = t >> 3;            // 0..31
    const int c16 = t & 7;
    const uint32_t dstA = sbase + SM_A + buf * 16384;
    const uint32_t dstB = sbase + SM_B + buf * 16384;
    const __half* srcA = g_u16 + (size_t)(i0 + row) * C_S + kcg * 64 + c16 * 8;
    const __half* srcB = g_ball + (size_t)j * (C_Z * C_S) + (size_t)row * C_S
                         + kcg * 64 + c16 * 8;
    const uint32_t sw = (uint32_t)(((c16 ^ (row & 7)) & 7) * 16 + row * 128);
    #pragma unroll
    for (int q = 0; q < 4; q++) {
        uint32_t off = sw + q * 32 * 128;
        CP_ASYNC16(dstA + off, srcA + (size_t)q * 32 * C_S);
        CP_ASYNC16(dstB + off, srcB + (size_t)q * 32 * C_S);
    }
}

__global__ __launch_bounds__(256, 2)
void pair_kernel(const int* __restrict__ chain,
                 const int* __restrict__ ridx,
                 const float* __restrict__ E_cp,
                 const float* __restrict__ E_rp,
                 float* __restrict__ out_z)
{
    extern __shared__ char smem[];
    const uint32_t sbase = smem_u32(smem);
    const int t = threadIdx.x;           // 256
    const int lane = t & 31, wid = t >> 5;
    const int wm = wid >> 2;             // 0..1  (M)
    const int wn = wid & 3;              // 0..3  (N)

    float* ecp_s = (float*)(smem + SM_ECP);
    float* zjb_s = (float*)(smem + SM_ZJB);
    float* zib_s = (float*)(smem + SM_ZIBJ);
    int*   ch_s  = (int*)  (smem + SM_CH);
    int*   ri_s  = (int*)  (smem + SM_RI);

    for (int idx = t; idx < 4 * C_Z; idx += 256)
        ecp_s[(idx >> 7) * 132 + (idx & 127)] = E_cp[idx];

    // lane address components (ldmatrix)
    const int arow_l = lane & 15;
    const int achk_l = lane >> 4;
    const int bgrp   = lane >> 3;
    const int bz_l   = ((bgrp >> 1) << 3) + (lane & 7);
    const int bco    = bgrp & 1;

    #pragma unroll 1
    for (int u = blockIdx.x; u < NUNITS; u += GRID_PAIR) {
        // decode unit -> (by, j)
        int by, j;
        if (u < 512)       { by = 0; j = u; }
        else if (u < 896)  { by = 1; j = u - 512 + 128; }
        else if (u < 1152) { by = 2; j = u - 896 + 256; }
        else               { by = 3; j = u - 1152 + 384; }
        const int i0 = by * 128;
        const bool mirror = (j >= i0 + 128);

        __syncthreads();   // previous unit fully done before restaging

        stage_async(sbase, 0, 0, i0, j, t); CP_COMMIT();
        stage_async(sbase, 1, 1, i0, j, t); CP_COMMIT();

        if (t < 128) {
            zjb_s[t] = g_zjb[(size_t)j * C_Z + t];
            zib_s[t] = g_zib[(size_t)j * C_Z + t];
        } else {
            int tt = t - 128;
            ch_s[tt] = chain[i0 + tt];
            ri_s[tt] = ridx[i0 + tt];
        }
        const int cjv = chain[j], rjv = ridx[j];

        float acc[4][4][4];
        #pragma unroll
        for (int mt = 0; mt < 4; mt++)
            #pragma unroll
            for (int nt = 0; nt < 4; nt++)
                #pragma unroll
                for (int q = 0; q < 4; q++) acc[mt][nt][q] = 0.f;

        #pragma unroll
        for (int kcg = 0; kcg < NCHUNK; kcg++) {
            if (kcg < NCHUNK - 1) { CP_WAIT1(); } else { CP_WAIT0(); }
            __syncthreads();

            const uint32_t apb = sbase + SM_A + (kcg & 1) * 16384;
            const uint32_t bpb = sbase + SM_B + (kcg & 1) * 16384;
            #pragma unroll
            for (int kk = 0; kk < 4; kk++) {
                uint32_t bh[4][2];
                #pragma unroll
                for (int pair = 0; pair < 2; pair++) {
                    int z = wn * 32 + pair * 16 + bz_l;
                    ldsm_x4(bh[pair*2][0], bh[pair*2][1],
                            bh[pair*2+1][0], bh[pair*2+1][1],
                            bpb + sw_off(z, kk * 2 + bco));
                }
                uint32_t ahf[4][4];
                #pragma unroll
                for (int mt = 0; mt < 4; mt++) {
                    int row = wm * 64 + mt * 16 + arow_l;
                    ldsm_x4(ahf[mt][0], ahf[mt][1], ahf[mt][2], ahf[mt][3],
                            apb + sw_off(row, kk * 2 + achk_l));
                }
                #pragma unroll
                for (int mt = 0; mt < 4; mt++)
                    #pragma unroll
                    for (int nt = 0; nt < 4; nt++)
                        mma16816(acc[mt][nt], ahf[mt], bh[nt]);
            }

            if (kcg < NCHUNK - 2) {
                __syncthreads();           // all warps done reading buf kcg&1
                stage_async(sbase, kcg & 1, kcg + 2, i0, j, t);
                CP_COMMIT();
            }
        }

        // ---- epilogue ----
        const int g = lane >> 2, tig = lane & 3;
        #pragma unroll
        for (int mt = 0; mt < 4; mt++) {
            #pragma unroll
            for (int h = 0; h < 2; h++) {
                int row_l = wm * 64 + mt * 16 + g + h * 8;
                int irow = i0 + row_l;
                int ci = ch_s[row_l], ri = ri_s[row_l];
                int samec = (ci == cjv);
                int dd = ri - rjv;
                int dcl = dd < -32 ? -32 : (dd > 32 ? 32 : dd);

                // direct: z[irow, j, :]
                {
                    int cp = ci * 2 + cjv;
                    int rp = samec ? (dcl + 32) : 65;
                    const float* erow = E_rp + (size_t)rp * C_Z;
                    const float* crow = ecp_s + cp * 132;
                    const float* zir  = g_zib + (size_t)irow * C_Z;
                    float* orow = out_z + ((size_t)irow * L_RES + j) * C_Z;
                    #pragma unroll
                    for (int nt = 0; nt < 4; nt++) {
                        int col = wn * 32 + nt * 8 + tig * 2;
                        float2 zi2 = *(const float2*)(zir + col);
                        float2 zj2 = *(const float2*)(zjb_s + col);
                        float2 ec2 = *(const float2*)(crow + col);
                        float2 er2 = *(const float2*)(erow + col);
                        float2 o;
                        o.x = acc[mt][nt][h * 2]     + zi2.x + zj2.x + ec2.x + er2.x;
                        o.y = acc[mt][nt][h * 2 + 1] + zi2.y + zj2.y + ec2.y + er2.y;
                        *(float2*)(orow + col) = o;
                    }
                }
                // mirror: z[j, irow, :]
                if (mirror) {
                    int cp = cjv * 2 + ci;
                    int rp = samec ? (32 - dcl) : 65;
                    const float* erow = E_rp + (size_t)rp * C_Z;
                    const float* crow = ecp_s + cp * 132;
                    const float* zjr  = g_zjb + (size_t)irow * C_Z;
                    float* orow = out_z + ((size_t)j * L_RES + irow) * C_Z;
                    #pragma unroll
                    for (int nt = 0; nt < 4; nt++) {
                        int col = wn * 32 + nt * 8 + tig * 2;
                        float2 zi2 = *(const float2*)(zib_s + col);
                        float2 zj2 = *(const float2*)(zjr + col);
                        float2 ec2 = *(const float2*)(crow + col);
                        float2 er2 = *(const float2*)(erow + col);
                        float2 o;
                        o.x = acc[mt][nt][h * 2]     + zi2.x + zj2.x + ec2.x + er2.x;
                        o.y = acc[mt][nt][h * 2 + 1] + zi2.y + zj2.y + ec2.y + er2.y;
                        *(float2*)(orow + col) = o;
                    }
                }
            }
        }
    }
}

// ---------------------------------------------------------------------------
extern "C" void kernel_launch(void* const* d_in, const int* in_sizes, int n_in,
                              void* d_out, int out_size)
{
    const int*   seq     = (const int*)  d_in[0];
    const int*   chain   = (const int*)  d_in[1];
    const int*   ridx    = (const int*)  d_in[2];
    const float* E_aa    = (const float*)d_in[3];
    const float* E_pos   = (const float*)d_in[4];
    const float* E_chain = (const float*)d_in[5];
    const float* E_cp    = (const float*)d_in[6];
    const float* E_rp    = (const float*)d_in[7];
    const float* W_pair  = (const float*)d_in[8];
    const float* b_pair  = (const float*)d_in[9];
    const float* ln_w    = (const float*)d_in[10];
    const float* ln_b    = (const float*)d_in[11];

    float* out_s = (float*)d_out;
    float* out_z = out_s + (size_t)L_RES * C_S;

    static int smem_set = 0;
    if (!smem_set) {
        cudaFuncSetAttribute(pair_kernel, cudaFuncAttributeMaxDynamicSharedMemorySize,
                             SMEM_TOTAL);
        smem_set = 1;
    }

    prep_kernel<<<128, 256>>>(seq, chain, ridx, E_aa, E_pos, E_chain,
                              W_pair, ln_w, ln_b, out_s);
    gemv_kernel<<<128, 256>>>(W_pair, b_pair);
    bprep_kernel<<<L_RES, 256>>>();
    pair_kernel<<<GRID_PAIR, 256, SMEM_TOTAL>>>(chain, ridx, E_cp, E_rp, out_z);
}